// round 15
// baseline (speedup 1.0000x reference)
#include <cuda_runtime.h>
#include <math.h>

// ---------------- problem constants ----------------
#define MROWS 4096            // B*T*N rows
#define DDIM  1152
#define NHEAD 16
#define HDIM  72
#define IDIM  4304
#define NPATCH 1024
#define KCONV 588             // 14*14*3
#define NLAYER 4

// ---------------- scratch (device globals; no allocations allowed) ----------
__device__ float g_x   [(size_t)MROWS*DDIM];
__device__ float g_h   [(size_t)MROWS*DDIM];
__device__ float g_q   [(size_t)MROWS*DDIM];
__device__ float g_k   [(size_t)MROWS*DDIM];
__device__ float g_v   [(size_t)MROWS*DDIM];
__device__ float g_attn[(size_t)MROWS*DDIM];
__device__ float g_mlp [(size_t)MROWS*IDIM];
__device__ float g_scor[(size_t)64*1024*1024];   // 64 (b,h) x 1024 x 1024
__device__ float g_col [(size_t)MROWS*KCONV];

// ---------------- im2col (stride == kernel, non-overlapping) ----------------
__global__ void im2col_k(const float* __restrict__ img, float* __restrict__ col) {
    int idx = blockIdx.x * blockDim.x + threadIdx.x;   // over 4096*588
    if (idx >= MROWS * KCONV) return;
    int p = idx / KCONV, j = idx % KCONV;
    int im = p >> 10;            // image 0..3
    int pr = (p >> 5) & 31;      // patch row
    int pc = p & 31;             // patch col
    int c  = j % 3;
    int t  = j / 3;
    int kx = t % 14, ky = t / 14;
    int y = pr * 14 + ky, x = pc * 14 + kx;
    col[idx] = img[(((size_t)im * 448 + y) * 448 + x) * 3 + c];
}

// ---------------- reductions ----------------
__device__ __forceinline__ float warp_sum(float v) {
    #pragma unroll
    for (int o = 16; o; o >>= 1) v += __shfl_xor_sync(0xffffffffu, v, o);
    return v;
}
__device__ __forceinline__ float warp_max(float v) {
    #pragma unroll
    for (int o = 16; o; o >>= 1) v = fmaxf(v, __shfl_xor_sync(0xffffffffu, v, o));
    return v;
}

// ---------------- layernorm ----------------
__global__ void layernorm_k(const float* __restrict__ in, float* __restrict__ out,
                            const float* __restrict__ g, const float* __restrict__ b) {
    size_t row = blockIdx.x;
    const float* x = in + row * DDIM;
    float s = 0.f, s2 = 0.f;
    for (int i = threadIdx.x; i < DDIM; i += 256) { float v = x[i]; s += v; s2 += v * v; }
    __shared__ float sh0[8], sh1[8];
    s = warp_sum(s); s2 = warp_sum(s2);
    int w = threadIdx.x >> 5, l = threadIdx.x & 31;
    if (!l) { sh0[w] = s; sh1[w] = s2; }
    __syncthreads();
    if (w == 0) {
        float a = (l < 8) ? sh0[l] : 0.f;
        float c = (l < 8) ? sh1[l] : 0.f;
        a = warp_sum(a); c = warp_sum(c);
        if (!l) { sh0[0] = a; sh1[0] = c; }
    }
    __syncthreads();
    float mu  = sh0[0] * (1.f / DDIM);
    float var = sh1[0] * (1.f / DDIM) - mu * mu;
    float inv = rsqrtf(var + 1e-6f);
    float* o = out + row * DDIM;
    for (int i = threadIdx.x; i < DDIM; i += 256)
        o[i] = (x[i] - mu) * inv * g[i] + b[i];
}

// ---------------- softmax ----------------
__global__ void softmax_k(float* __restrict__ s) {
    size_t row = blockIdx.x;
    float* p = s + row * 1024;
    __shared__ float sh[8];
    int w = threadIdx.x >> 5, l = threadIdx.x & 31;
    float mx = -1e30f;
    for (int i = threadIdx.x; i < 1024; i += 256) mx = fmaxf(mx, p[i]);
    mx = warp_max(mx);
    if (!l) sh[w] = mx;
    __syncthreads();
    if (w == 0) { float a = (l < 8) ? sh[l] : -1e30f; a = warp_max(a); if (!l) sh[0] = a; }
    __syncthreads();
    mx = sh[0];
    __syncthreads();
    float sum = 0.f;
    for (int i = threadIdx.x; i < 1024; i += 256) {
        float e = __expf(p[i] - mx);
        p[i] = e; sum += e;
    }
    sum = warp_sum(sum);
    if (!l) sh[w] = sum;
    __syncthreads();
    if (w == 0) { float a = (l < 8) ? sh[l] : 0.f; a = warp_sum(a); if (!l) sh[0] = a; }
    __syncthreads();
    float inv = 1.f / sh[0];
    for (int i = threadIdx.x; i < 1024; i += 256) p[i] *= inv;
}

// ---------------- tf32 tensor-core GEMM, fragment-permuted smem -------------
// C[M,N] = alpha * A[M,K] * op(B) (+bias[n]) (+posemb) (gelu) (+resid)
// Block 128x128x16, 8 warps (2m x 4n), warp tile 64x32 via m16n8k8 tf32 mma.
// Smem tiles stored pre-permuted into per-thread fragment order:
//   A frag (4 regs) -> one LDS.128 ; B frag (2 regs) -> one LDS.64
#define BM 128
#define BN 128
#define BK 16
#define FLAG_GELU 1

__device__ __forceinline__ unsigned f2tf32(float x) {
    unsigned u;
    asm("cvt.rna.tf32.f32 %0, %1;" : "=r"(u) : "f"(x));
    return u;
}

__device__ __forceinline__ void mma_tf32(float* c, const uint4 a, const uint2 b) {
    asm volatile(
        "mma.sync.aligned.m16n8k8.row.col.f32.tf32.tf32.f32 "
        "{%0,%1,%2,%3}, {%4,%5,%6,%7}, {%8,%9}, {%0,%1,%2,%3};\n"
        : "+f"(c[0]), "+f"(c[1]), "+f"(c[2]), "+f"(c[3])
        : "r"(a.x), "r"(a.y), "r"(a.z), "r"(a.w), "r"(b.x), "r"(b.y));
}

__device__ __forceinline__ float fast_gelu(float t) {
    // 0.5*t*(1+tanh(GC*(t + 0.044715 t^3))), tanh via exp2-based __expf, clamped
    const float GC = 0.7978845608028654f;
    float a = GC * (t + 0.044715f * t * t * t);
    a = fminf(fmaxf(a, -15.f), 15.f);
    float e = __expf(2.f * a);
    float th = (e - 1.f) / (e + 1.f);
    return 0.5f * t * (1.f + th);
}

template<bool TRANSB>
__global__ void __launch_bounds__(256, 2)
tgemm_k(const float* __restrict__ A, const float* __restrict__ B, float* __restrict__ C,
        int M, int N, int K, int lda, int ldb, int ldc,
        const float* __restrict__ bias, const float* __restrict__ resid,
        const float* __restrict__ posemb, float alpha, int flags, int bmode) {
    int z = blockIdx.z;
    if (bmode == 1) {
        int bb = z >> 4, hh = z & 15;
        size_t qk = (size_t)bb * 1024 * DDIM + (size_t)hh * HDIM;
        A += qk; B += qk; C += (size_t)z * 1024 * 1024;
    } else if (bmode == 2) {
        int bb = z >> 4, hh = z & 15;
        size_t vo = (size_t)bb * 1024 * DDIM + (size_t)hh * HDIM;
        A += (size_t)z * 1024 * 1024; B += vo; C += vo;
        if (resid) resid += vo;
    }

    // permuted tiles: A = [ks2][wm2][mt4][grp8][tig4][reg4]  (4096 u32)
    //                 B = [ks2][wn4][nt4][grp8][tig4][reg2]  (2048 u32)
    __shared__ unsigned As[2][4096];
    __shared__ unsigned Bs[2][2048];

    int bm = blockIdx.y * BM, bn = blockIdx.x * BN;
    int tid = threadIdx.x;
    int lane = tid & 31, wid = tid >> 5;
    int wmIdx = wid & 1,  wm = wmIdx * 64;      // 2 warps in m
    int wnIdx = wid >> 1, wn = wnIdx * 32;      // 4 warps in n
    int grp = lane >> 2, tig = lane & 3;

    // global-load thread mapping
    int ar  = tid >> 1, ac  = (tid & 1) * 4;   // A: 128 rows x (2 x float4 in k)
    int brr = tid >> 5, bcc = (tid & 31) * 4;  // B (no trans)
    int tn  = tid >> 1, tk  = (tid & 1) * 4;   // B (trans)

    // precomputed pieces of permuted write indices
    int a_wmI = ar >> 6, a_rr = ar & 63;
    int a_mt = a_rr >> 4, a_hr = (a_rr >> 3) & 1, a_g = a_rr & 7;
    int a_reg = a_hr + ((ac >> 2) << 1);

    float4 aReg[2], bReg[2];

    auto ldTiles = [&](int k0) {
        #pragma unroll
        for (int h = 0; h < 2; h++) {
            int gk = k0 + ac + h * 8;
            aReg[h] = (gk < K) ? *(const float4*)(A + (size_t)(bm + ar) * lda + gk)
                               : make_float4(0.f, 0.f, 0.f, 0.f);
        }
        if (!TRANSB) {
            #pragma unroll
            for (int h = 0; h < 2; h++) {
                int gk = k0 + brr + h * 8;
                int gn = bn + bcc;
                bReg[h] = (gk < K && gn < N)
                          ? *(const float4*)(B + (size_t)gk * ldb + gn)
                          : make_float4(0.f, 0.f, 0.f, 0.f);
            }
        } else {
            #pragma unroll
            for (int h = 0; h < 2; h++) {
                int gk = k0 + tk + h * 8;
                int gn = bn + tn;
                bReg[h] = (gk < K && gn < N)
                          ? *(const float4*)(B + (size_t)gn * ldb + gk)
                          : make_float4(0.f, 0.f, 0.f, 0.f);
            }
        }
    };

    auto stTiles = [&](int buf) {
        // A: element (ar, k=ac+h*8+j) -> [h][a_wmI][a_mt][a_g][j][a_reg]
        #pragma unroll
        for (int h = 0; h < 2; h++) {
            int base = (((h * 2 + a_wmI) * 4 + a_mt) * 8 + a_g) * 4;
            float vv[4] = {aReg[h].x, aReg[h].y, aReg[h].z, aReg[h].w};
            #pragma unroll
            for (int j = 0; j < 4; j++)
                As[buf][(base + j) * 4 + a_reg] = f2tf32(vv[j]);
        }
        if (!TRANSB) {
            // element (n=bcc+c, k=brr+h*8) -> [h][wnI][nt][g][tigB][half4]
            int tigB = brr & 3, half4 = brr >> 2;
            #pragma unroll
            for (int h = 0; h < 2; h++) {
                float vv[4] = {bReg[h].x, bReg[h].y, bReg[h].z, bReg[h].w};
                #pragma unroll
                for (int c = 0; c < 4; c++) {
                    int n = bcc + c;
                    int wnI = n >> 5, nn = n & 31, nt = nn >> 3, g = nn & 7;
                    Bs[buf][((((h * 4 + wnI) * 4 + nt) * 8 + g) * 4 + tigB) * 2 + half4]
                        = f2tf32(vv[c]);
                }
            }
        } else {
            // element (n=tn, k=tk+h*8+j) -> [h][wnI][nt][g][j][tk>>2]
            int wnI = tn >> 5, nt = (tn & 31) >> 3, g = tn & 7, half4 = tk >> 2;
            #pragma unroll
            for (int h = 0; h < 2; h++) {
                int base = (((h * 4 + wnI) * 4 + nt) * 8 + g) * 4;
                float vv[4] = {bReg[h].x, bReg[h].y, bReg[h].z, bReg[h].w};
                #pragma unroll
                for (int j = 0; j < 4; j++)
                    Bs[buf][(base + j) * 2 + half4] = f2tf32(vv[j]);
            }
        }
    };

    float acc[4][4][4];
    #pragma unroll
    for (int i = 0; i < 4; i++)
        #pragma unroll
        for (int j = 0; j < 4; j++)
            #pragma unroll
            for (int r = 0; r < 4; r++) acc[i][j][r] = 0.f;

    int nk = (K + BK - 1) / BK;
    ldTiles(0);
    stTiles(0);
    __syncthreads();

    for (int kt = 0; kt < nk; kt++) {
        int cur = kt & 1;
        bool more = (kt + 1 < nk);
        if (more) ldTiles((kt + 1) * BK);

        #pragma unroll
        for (int ks = 0; ks < 2; ks++) {
            uint4 a[4];
            uint2 b[4];
            int aStart = ((((ks * 2 + wmIdx) * 4) * 8 + grp) * 4 + tig) * 4;
            int bStart = ((((ks * 4 + wnIdx) * 4) * 8 + grp) * 4 + tig) * 2;
            #pragma unroll
            for (int mt = 0; mt < 4; mt++)
                a[mt] = *(const uint4*)&As[cur][aStart + mt * 128];
            #pragma unroll
            for (int nt = 0; nt < 4; nt++)
                b[nt] = *(const uint2*)&Bs[cur][bStart + nt * 64];
            #pragma unroll
            for (int mt = 0; mt < 4; mt++)
                #pragma unroll
                for (int nt = 0; nt < 4; nt++)
                    mma_tf32(acc[mt][nt], a[mt], b[nt]);
        }
        if (more) stTiles(cur ^ 1);
        __syncthreads();
    }

    // --- epilogue ---
    #pragma unroll
    for (int mt = 0; mt < 4; mt++) {
        #pragma unroll
        for (int nt = 0; nt < 4; nt++) {
            int gc = bn + wn + nt * 8 + 2 * tig;
            if (gc >= N) continue;
            #pragma unroll
            for (int half = 0; half < 2; half++) {
                int gm = bm + wm + mt * 16 + grp + half * 8;
                if (gm >= M) continue;
                float v0 = acc[mt][nt][half * 2 + 0] * alpha;
                float v1 = acc[mt][nt][half * 2 + 1] * alpha;
                if (bias)   { v0 += bias[gc]; v1 += bias[gc + 1]; }
                if (posemb) {
                    const float* pe = posemb + (size_t)(gm & (NPATCH - 1)) * DDIM;
                    v0 += pe[gc]; v1 += pe[gc + 1];
                }
                if (flags & FLAG_GELU) { v0 = fast_gelu(v0); v1 = fast_gelu(v1); }
                if (resid) {
                    v0 += resid[(size_t)gm * ldc + gc];
                    v1 += resid[(size_t)gm * ldc + gc + 1];
                }
                *(float2*)(C + (size_t)gm * ldc + gc) = make_float2(v0, v1);
            }
        }
    }
}

// ---------------- host-side helper ----------------
static void gemm(const float* A, const float* B, float* C,
                 int M, int N, int K, int lda, int ldb, int ldc,
                 const float* bias, const float* resid, const float* posemb,
                 float alpha, int flags, int bmode, int Z, bool transb) {
    dim3 grid((N + BN - 1) / BN, (M + BM - 1) / BM, Z);
    if (transb)
        tgemm_k<true ><<<grid, 256>>>(A, B, C, M, N, K, lda, ldb, ldc,
                                      bias, resid, posemb, alpha, flags, bmode);
    else
        tgemm_k<false><<<grid, 256>>>(A, B, C, M, N, K, lda, ldb, ldc,
                                      bias, resid, posemb, alpha, flags, bmode);
}

extern "C" void kernel_launch(void* const* d_in, const int* in_sizes, int n_in,
                              void* d_out, int out_size) {
    const float* images = (const float*)d_in[0];
    const float* conv_w = (const float*)d_in[1];
    const float* conv_b = (const float*)d_in[2];
    const float* posemb = (const float*)d_in[3];
    const float* ln1_g  = (const float*)d_in[4];
    const float* ln1_b  = (const float*)d_in[5];
    const float* Wq     = (const float*)d_in[6];
    const float* bq     = (const float*)d_in[7];
    const float* Wk     = (const float*)d_in[8];
    const float* bk     = (const float*)d_in[9];
    const float* Wv     = (const float*)d_in[10];
    const float* bv     = (const float*)d_in[11];
    const float* Wo     = (const float*)d_in[12];
    const float* bo     = (const float*)d_in[13];
    const float* ln2_g  = (const float*)d_in[14];
    const float* ln2_b  = (const float*)d_in[15];
    const float* W1     = (const float*)d_in[16];
    const float* b1     = (const float*)d_in[17];
    const float* W2     = (const float*)d_in[18];
    const float* b2     = (const float*)d_in[19];
    const float* lnf_g  = (const float*)d_in[20];
    const float* lnf_b  = (const float*)d_in[21];
    float* out = (float*)d_out;

    float *x, *h, *q, *k, *v, *attn, *mlp, *scor, *col;
    cudaGetSymbolAddress((void**)&x,    g_x);
    cudaGetSymbolAddress((void**)&h,    g_h);
    cudaGetSymbolAddress((void**)&q,    g_q);
    cudaGetSymbolAddress((void**)&k,    g_k);
    cudaGetSymbolAddress((void**)&v,    g_v);
    cudaGetSymbolAddress((void**)&attn, g_attn);
    cudaGetSymbolAddress((void**)&mlp,  g_mlp);
    cudaGetSymbolAddress((void**)&scor, g_scor);
    cudaGetSymbolAddress((void**)&col,  g_col);

    const float scale = 1.f / sqrtf((float)HDIM);

    // 1) patch embedding: im2col + GEMM (+conv_b +pos_emb) -> x
    {
        int tot = MROWS * KCONV;
        im2col_k<<<(tot + 255) / 256, 256>>>(images, col);
        gemm(col, conv_w, x, MROWS, DDIM, KCONV, KCONV, DDIM, DDIM,
             conv_b, nullptr, posemb, 1.f, 0, 0, 1, false);
    }

    // 2) transformer layers
    for (int l = 0; l < NLAYER; l++) {
        const float* wq = Wq + (size_t)l * DDIM * DDIM;
        const float* wk = Wk + (size_t)l * DDIM * DDIM;
        const float* wv = Wv + (size_t)l * DDIM * DDIM;
        const float* wo = Wo + (size_t)l * DDIM * DDIM;
        const float* w1 = W1 + (size_t)l * DDIM * IDIM;
        const float* w2 = W2 + (size_t)l * IDIM * DDIM;

        layernorm_k<<<MROWS, 256>>>(x, h, ln1_g + l * DDIM, ln1_b + l * DDIM);

        gemm(h, wq, q, MROWS, DDIM, DDIM, DDIM, DDIM, DDIM,
             bq + l * DDIM, nullptr, nullptr, 1.f, 0, 0, 1, false);
        gemm(h, wk, k, MROWS, DDIM, DDIM, DDIM, DDIM, DDIM,
             bk + l * DDIM, nullptr, nullptr, 1.f, 0, 0, 1, false);
        gemm(h, wv, v, MROWS, DDIM, DDIM, DDIM, DDIM, DDIM,
             bv + l * DDIM, nullptr, nullptr, 1.f, 0, 0, 1, false);

        // scores[z] = scale * Q K^T   (z = b*16 + h, 64 batches)
        gemm(q, k, scor, 1024, 1024, HDIM, DDIM, DDIM, 1024,
             nullptr, nullptr, nullptr, scale, 0, 1, 64, true);

        softmax_k<<<64 * 1024, 256>>>(scor);

        // attn[z] = P V
        gemm(scor, v, attn, 1024, HDIM, 1024, 1024, DDIM, DDIM,
             nullptr, nullptr, nullptr, 1.f, 0, 2, 64, false);

        // x = x + attn @ Wo + bo
        gemm(attn, wo, x, MROWS, DDIM, DDIM, DDIM, DDIM, DDIM,
             bo + l * DDIM, x, nullptr, 1.f, 0, 0, 1, false);

        layernorm_k<<<MROWS, 256>>>(x, h, ln2_g + l * DDIM, ln2_b + l * DDIM);

        // mlp = gelu(h @ W1 + b1)
        gemm(h, w1, mlp, MROWS, IDIM, DDIM, DDIM, IDIM, IDIM,
             b1 + l * IDIM, nullptr, nullptr, 1.f, FLAG_GELU, 0, 1, false);

        // x = x + mlp @ W2 + b2
        gemm(mlp, w2, x, MROWS, DDIM, IDIM, IDIM, DDIM, DDIM,
             b2 + l * DDIM, x, nullptr, 1.f, 0, 0, 1, false);
    }

    // 3) final layernorm -> d_out
    layernorm_k<<<MROWS, 256>>>(x, out, lnf_g, lnf_b);
}

// round 16
// speedup vs baseline: 1.0023x; 1.0023x over previous
#include <cuda_runtime.h>
#include <math.h>

// ---------------- problem constants ----------------
#define MROWS 4096            // B*T*N rows
#define DDIM  1152
#define NHEAD 16
#define HDIM  72
#define IDIM  4304
#define NPATCH 1024
#define KCONV 588             // 14*14*3
#define NLAYER 4

// ---------------- scratch (device globals; no allocations allowed) ----------
__device__ float g_x   [(size_t)MROWS*DDIM];
__device__ float g_h   [(size_t)MROWS*DDIM];
__device__ float g_q   [(size_t)MROWS*DDIM];
__device__ float g_k   [(size_t)MROWS*DDIM];
__device__ float g_v   [(size_t)MROWS*DDIM];
__device__ float g_attn[(size_t)MROWS*DDIM];
__device__ float g_mlp [(size_t)MROWS*IDIM];
__device__ float g_scor[(size_t)64*1024*1024];   // 64 (b,h) x 1024 x 1024
__device__ float g_col [(size_t)MROWS*KCONV];

// ---------------- im2col (stride == kernel, non-overlapping) ----------------
__global__ void im2col_k(const float* __restrict__ img, float* __restrict__ col) {
    int idx = blockIdx.x * blockDim.x + threadIdx.x;   // over 4096*588
    if (idx >= MROWS * KCONV) return;
    int p = idx / KCONV, j = idx % KCONV;
    int im = p >> 10;            // image 0..3
    int pr = (p >> 5) & 31;      // patch row
    int pc = p & 31;             // patch col
    int c  = j % 3;
    int t  = j / 3;
    int kx = t % 14, ky = t / 14;
    int y = pr * 14 + ky, x = pc * 14 + kx;
    col[idx] = img[(((size_t)im * 448 + y) * 448 + x) * 3 + c];
}

// ---------------- reductions ----------------
__device__ __forceinline__ float warp_sum(float v) {
    #pragma unroll
    for (int o = 16; o; o >>= 1) v += __shfl_xor_sync(0xffffffffu, v, o);
    return v;
}
__device__ __forceinline__ float warp_max(float v) {
    #pragma unroll
    for (int o = 16; o; o >>= 1) v = fmaxf(v, __shfl_xor_sync(0xffffffffu, v, o));
    return v;
}

// ---------------- layernorm ----------------
__global__ void layernorm_k(const float* __restrict__ in, float* __restrict__ out,
                            const float* __restrict__ g, const float* __restrict__ b) {
    size_t row = blockIdx.x;
    const float* x = in + row * DDIM;
    float s = 0.f, s2 = 0.f;
    for (int i = threadIdx.x; i < DDIM; i += 256) { float v = x[i]; s += v; s2 += v * v; }
    __shared__ float sh0[8], sh1[8];
    s = warp_sum(s); s2 = warp_sum(s2);
    int w = threadIdx.x >> 5, l = threadIdx.x & 31;
    if (!l) { sh0[w] = s; sh1[w] = s2; }
    __syncthreads();
    if (w == 0) {
        float a = (l < 8) ? sh0[l] : 0.f;
        float c = (l < 8) ? sh1[l] : 0.f;
        a = warp_sum(a); c = warp_sum(c);
        if (!l) { sh0[0] = a; sh1[0] = c; }
    }
    __syncthreads();
    float mu  = sh0[0] * (1.f / DDIM);
    float var = sh1[0] * (1.f / DDIM) - mu * mu;
    float inv = rsqrtf(var + 1e-6f);
    float* o = out + row * DDIM;
    for (int i = threadIdx.x; i < DDIM; i += 256)
        o[i] = (x[i] - mu) * inv * g[i] + b[i];
}

// ---------------- softmax ----------------
__global__ void softmax_k(float* __restrict__ s) {
    size_t row = blockIdx.x;
    float* p = s + row * 1024;
    __shared__ float sh[8];
    int w = threadIdx.x >> 5, l = threadIdx.x & 31;
    float mx = -1e30f;
    for (int i = threadIdx.x; i < 1024; i += 256) mx = fmaxf(mx, p[i]);
    mx = warp_max(mx);
    if (!l) sh[w] = mx;
    __syncthreads();
    if (w == 0) { float a = (l < 8) ? sh[l] : -1e30f; a = warp_max(a); if (!l) sh[0] = a; }
    __syncthreads();
    mx = sh[0];
    __syncthreads();
    float sum = 0.f;
    for (int i = threadIdx.x; i < 1024; i += 256) {
        float e = __expf(p[i] - mx);
        p[i] = e; sum += e;
    }
    sum = warp_sum(sum);
    if (!l) sh[w] = sum;
    __syncthreads();
    if (w == 0) { float a = (l < 8) ? sh[l] : 0.f; a = warp_sum(a); if (!l) sh[0] = a; }
    __syncthreads();
    float inv = 1.f / sh[0];
    for (int i = threadIdx.x; i < 1024; i += 256) p[i] *= inv;
}

// ---------------- tf32 tensor-core GEMM, fragment-permuted smem -------------
// C[M,N] = alpha * A[M,K] * op(B) (+bias[n]) (+posemb) (gelu) (+resid)
// Block 128x128x16, 8 warps (2m x 4n), warp tile 64x32 via m16n8k8 tf32 mma.
// Smem tiles stored pre-permuted into per-thread fragment order:
//   A frag (4 regs) -> one LDS.128 ; B frag (2 regs) -> one LDS.64
#define BM 128
#define BN 128
#define BK 16
#define FLAG_GELU 1

__device__ __forceinline__ unsigned f2tf32(float x) {
    unsigned u;
    asm("cvt.rna.tf32.f32 %0, %1;" : "=r"(u) : "f"(x));
    return u;
}

__device__ __forceinline__ void mma_tf32(float* c, const uint4 a, const uint2 b) {
    asm volatile(
        "mma.sync.aligned.m16n8k8.row.col.f32.tf32.tf32.f32 "
        "{%0,%1,%2,%3}, {%4,%5,%6,%7}, {%8,%9}, {%0,%1,%2,%3};\n"
        : "+f"(c[0]), "+f"(c[1]), "+f"(c[2]), "+f"(c[3])
        : "r"(a.x), "r"(a.y), "r"(a.z), "r"(a.w), "r"(b.x), "r"(b.y));
}

__device__ __forceinline__ float fast_gelu(float t) {
    // 0.5*t*(1+tanh(GC*(t + 0.044715 t^3))), tanh via exp2-based __expf, clamped
    const float GC = 0.7978845608028654f;
    float a = GC * (t + 0.044715f * t * t * t);
    a = fminf(fmaxf(a, -15.f), 15.f);
    float e = __expf(2.f * a);
    float th = (e - 1.f) / (e + 1.f);
    return 0.5f * t * (1.f + th);
}

template<bool TRANSB>
__global__ void __launch_bounds__(256, 2)
tgemm_k(const float* __restrict__ A, const float* __restrict__ B, float* __restrict__ C,
        int M, int N, int K, int lda, int ldb, int ldc,
        const float* __restrict__ bias, const float* __restrict__ resid,
        const float* __restrict__ posemb, float alpha, int flags, int bmode) {
    int z = blockIdx.z;
    if (bmode == 1) {
        int bb = z >> 4, hh = z & 15;
        size_t qk = (size_t)bb * 1024 * DDIM + (size_t)hh * HDIM;
        A += qk; B += qk; C += (size_t)z * 1024 * 1024;
    } else if (bmode == 2) {
        int bb = z >> 4, hh = z & 15;
        size_t vo = (size_t)bb * 1024 * DDIM + (size_t)hh * HDIM;
        A += (size_t)z * 1024 * 1024; B += vo; C += vo;
        if (resid) resid += vo;
    }

    // permuted tiles: A = [ks2][wm2][mt4][grp8][tig4][reg4]  (4096 u32)
    //                 B = [ks2][wn4][nt4][grp8][tig4][reg2]  (2048 u32)
    __shared__ unsigned As[2][4096];
    __shared__ unsigned Bs[2][2048];

    int bm = blockIdx.y * BM, bn = blockIdx.x * BN;
    int tid = threadIdx.x;
    int lane = tid & 31, wid = tid >> 5;
    int wmIdx = wid & 1,  wm = wmIdx * 64;      // 2 warps in m
    int wnIdx = wid >> 1, wn = wnIdx * 32;      // 4 warps in n
    int grp = lane >> 2, tig = lane & 3;

    // global-load thread mapping
    int ar  = tid >> 1, ac  = (tid & 1) * 4;   // A: 128 rows x (2 x float4 in k)
    int brr = tid >> 5, bcc = (tid & 31) * 4;  // B (no trans)
    int tn  = tid >> 1, tk  = (tid & 1) * 4;   // B (trans)

    // precomputed pieces of permuted write indices
    int a_wmI = ar >> 6, a_rr = ar & 63;
    int a_mt = a_rr >> 4, a_hr = (a_rr >> 3) & 1, a_g = a_rr & 7;
    int a_reg = a_hr + ((ac >> 2) << 1);

    float4 aReg[2], bReg[2];

    auto ldTiles = [&](int k0) {
        #pragma unroll
        for (int h = 0; h < 2; h++) {
            int gk = k0 + ac + h * 8;
            aReg[h] = (gk < K) ? *(const float4*)(A + (size_t)(bm + ar) * lda + gk)
                               : make_float4(0.f, 0.f, 0.f, 0.f);
        }
        if (!TRANSB) {
            #pragma unroll
            for (int h = 0; h < 2; h++) {
                int gk = k0 + brr + h * 8;
                int gn = bn + bcc;
                bReg[h] = (gk < K && gn < N)
                          ? *(const float4*)(B + (size_t)gk * ldb + gn)
                          : make_float4(0.f, 0.f, 0.f, 0.f);
            }
        } else {
            #pragma unroll
            for (int h = 0; h < 2; h++) {
                int gk = k0 + tk + h * 8;
                int gn = bn + tn;
                bReg[h] = (gk < K && gn < N)
                          ? *(const float4*)(B + (size_t)gn * ldb + gk)
                          : make_float4(0.f, 0.f, 0.f, 0.f);
            }
        }
    };

    auto stTiles = [&](int buf) {
        // A: element (ar, k=ac+h*8+j) -> [h][a_wmI][a_mt][a_g][j][a_reg]
        #pragma unroll
        for (int h = 0; h < 2; h++) {
            int base = (((h * 2 + a_wmI) * 4 + a_mt) * 8 + a_g) * 4;
            float vv[4] = {aReg[h].x, aReg[h].y, aReg[h].z, aReg[h].w};
            #pragma unroll
            for (int j = 0; j < 4; j++)
                As[buf][(base + j) * 4 + a_reg] = f2tf32(vv[j]);
        }
        if (!TRANSB) {
            // element (n=bcc+c, k=brr+h*8) -> [h][wnI][nt][g][tigB][half4]
            int tigB = brr & 3, half4 = brr >> 2;
            #pragma unroll
            for (int h = 0; h < 2; h++) {
                float vv[4] = {bReg[h].x, bReg[h].y, bReg[h].z, bReg[h].w};
                #pragma unroll
                for (int c = 0; c < 4; c++) {
                    int n = bcc + c;
                    int wnI = n >> 5, nn = n & 31, nt = nn >> 3, g = nn & 7;
                    Bs[buf][((((h * 4 + wnI) * 4 + nt) * 8 + g) * 4 + tigB) * 2 + half4]
                        = f2tf32(vv[c]);
                }
            }
        } else {
            // element (n=tn, k=tk+h*8+j) -> [h][wnI][nt][g][j][tk>>2]
            int wnI = tn >> 5, nt = (tn & 31) >> 3, g = tn & 7, half4 = tk >> 2;
            #pragma unroll
            for (int h = 0; h < 2; h++) {
                int base = (((h * 4 + wnI) * 4 + nt) * 8 + g) * 4;
                float vv[4] = {bReg[h].x, bReg[h].y, bReg[h].z, bReg[h].w};
                #pragma unroll
                for (int j = 0; j < 4; j++)
                    Bs[buf][(base + j) * 2 + half4] = f2tf32(vv[j]);
            }
        }
    };

    float acc[4][4][4];
    #pragma unroll
    for (int i = 0; i < 4; i++)
        #pragma unroll
        for (int j = 0; j < 4; j++)
            #pragma unroll
            for (int r = 0; r < 4; r++) acc[i][j][r] = 0.f;

    int nk = (K + BK - 1) / BK;
    ldTiles(0);
    stTiles(0);
    __syncthreads();

    for (int kt = 0; kt < nk; kt++) {
        int cur = kt & 1;
        bool more = (kt + 1 < nk);
        if (more) ldTiles((kt + 1) * BK);

        #pragma unroll
        for (int ks = 0; ks < 2; ks++) {
            uint4 a[4];
            uint2 b[4];
            int aStart = ((((ks * 2 + wmIdx) * 4) * 8 + grp) * 4 + tig) * 4;
            int bStart = ((((ks * 4 + wnIdx) * 4) * 8 + grp) * 4 + tig) * 2;
            #pragma unroll
            for (int mt = 0; mt < 4; mt++)
                a[mt] = *(const uint4*)&As[cur][aStart + mt * 128];
            #pragma unroll
            for (int nt = 0; nt < 4; nt++)
                b[nt] = *(const uint2*)&Bs[cur][bStart + nt * 64];
            #pragma unroll
            for (int mt = 0; mt < 4; mt++)
                #pragma unroll
                for (int nt = 0; nt < 4; nt++)
                    mma_tf32(acc[mt][nt], a[mt], b[nt]);
        }
        if (more) stTiles(cur ^ 1);
        __syncthreads();
    }

    // --- epilogue ---
    #pragma unroll
    for (int mt = 0; mt < 4; mt++) {
        #pragma unroll
        for (int nt = 0; nt < 4; nt++) {
            int gc = bn + wn + nt * 8 + 2 * tig;
            if (gc >= N) continue;
            #pragma unroll
            for (int half = 0; half < 2; half++) {
                int gm = bm + wm + mt * 16 + grp + half * 8;
                if (gm >= M) continue;
                float v0 = acc[mt][nt][half * 2 + 0] * alpha;
                float v1 = acc[mt][nt][half * 2 + 1] * alpha;
                if (bias)   { v0 += bias[gc]; v1 += bias[gc + 1]; }
                if (posemb) {
                    const float* pe = posemb + (size_t)(gm & (NPATCH - 1)) * DDIM;
                    v0 += pe[gc]; v1 += pe[gc + 1];
                }
                if (flags & FLAG_GELU) { v0 = fast_gelu(v0); v1 = fast_gelu(v1); }
                if (resid) {
                    v0 += resid[(size_t)gm * ldc + gc];
                    v1 += resid[(size_t)gm * ldc + gc + 1];
                }
                *(float2*)(C + (size_t)gm * ldc + gc) = make_float2(v0, v1);
            }
        }
    }
}

// ---------------- host-side helper ----------------
static void gemm(const float* A, const float* B, float* C,
                 int M, int N, int K, int lda, int ldb, int ldc,
                 const float* bias, const float* resid, const float* posemb,
                 float alpha, int flags, int bmode, int Z, bool transb) {
    dim3 grid((N + BN - 1) / BN, (M + BM - 1) / BM, Z);
    if (transb)
        tgemm_k<true ><<<grid, 256>>>(A, B, C, M, N, K, lda, ldb, ldc,
                                      bias, resid, posemb, alpha, flags, bmode);
    else
        tgemm_k<false><<<grid, 256>>>(A, B, C, M, N, K, lda, ldb, ldc,
                                      bias, resid, posemb, alpha, flags, bmode);
}

extern "C" void kernel_launch(void* const* d_in, const int* in_sizes, int n_in,
                              void* d_out, int out_size) {
    const float* images = (const float*)d_in[0];
    const float* conv_w = (const float*)d_in[1];
    const float* conv_b = (const float*)d_in[2];
    const float* posemb = (const float*)d_in[3];
    const float* ln1_g  = (const float*)d_in[4];
    const float* ln1_b  = (const float*)d_in[5];
    const float* Wq     = (const float*)d_in[6];
    const float* bq     = (const float*)d_in[7];
    const float* Wk     = (const float*)d_in[8];
    const float* bk     = (const float*)d_in[9];
    const float* Wv     = (const float*)d_in[10];
    const float* bv     = (const float*)d_in[11];
    const float* Wo     = (const float*)d_in[12];
    const float* bo     = (const float*)d_in[13];
    const float* ln2_g  = (const float*)d_in[14];
    const float* ln2_b  = (const float*)d_in[15];
    const float* W1     = (const float*)d_in[16];
    const float* b1     = (const float*)d_in[17];
    const float* W2     = (const float*)d_in[18];
    const float* b2     = (const float*)d_in[19];
    const float* lnf_g  = (const float*)d_in[20];
    const float* lnf_b  = (const float*)d_in[21];
    float* out = (float*)d_out;

    float *x, *h, *q, *k, *v, *attn, *mlp, *scor, *col;
    cudaGetSymbolAddress((void**)&x,    g_x);
    cudaGetSymbolAddress((void**)&h,    g_h);
    cudaGetSymbolAddress((void**)&q,    g_q);
    cudaGetSymbolAddress((void**)&k,    g_k);
    cudaGetSymbolAddress((void**)&v,    g_v);
    cudaGetSymbolAddress((void**)&attn, g_attn);
    cudaGetSymbolAddress((void**)&mlp,  g_mlp);
    cudaGetSymbolAddress((void**)&scor, g_scor);
    cudaGetSymbolAddress((void**)&col,  g_col);

    const float scale = 1.f / sqrtf((float)HDIM);

    // 1) patch embedding: im2col + GEMM (+conv_b +pos_emb) -> x
    {
        int tot = MROWS * KCONV;
        im2col_k<<<(tot + 255) / 256, 256>>>(images, col);
        gemm(col, conv_w, x, MROWS, DDIM, KCONV, KCONV, DDIM, DDIM,
             conv_b, nullptr, posemb, 1.f, 0, 0, 1, false);
    }

    // 2) transformer layers
    for (int l = 0; l < NLAYER; l++) {
        const float* wq = Wq + (size_t)l * DDIM * DDIM;
        const float* wk = Wk + (size_t)l * DDIM * DDIM;
        const float* wv = Wv + (size_t)l * DDIM * DDIM;
        const float* wo = Wo + (size_t)l * DDIM * DDIM;
        const float* w1 = W1 + (size_t)l * DDIM * IDIM;
        const float* w2 = W2 + (size_t)l * IDIM * DDIM;

        layernorm_k<<<MROWS, 256>>>(x, h, ln1_g + l * DDIM, ln1_b + l * DDIM);

        gemm(h, wq, q, MROWS, DDIM, DDIM, DDIM, DDIM, DDIM,
             bq + l * DDIM, nullptr, nullptr, 1.f, 0, 0, 1, false);
        gemm(h, wk, k, MROWS, DDIM, DDIM, DDIM, DDIM, DDIM,
             bk + l * DDIM, nullptr, nullptr, 1.f, 0, 0, 1, false);
        gemm(h, wv, v, MROWS, DDIM, DDIM, DDIM, DDIM, DDIM,
             bv + l * DDIM, nullptr, nullptr, 1.f, 0, 0, 1, false);

        // scores[z] = scale * Q K^T   (z = b*16 + h, 64 batches)
        gemm(q, k, scor, 1024, 1024, HDIM, DDIM, DDIM, 1024,
             nullptr, nullptr, nullptr, scale, 0, 1, 64, true);

        softmax_k<<<64 * 1024, 256>>>(scor);

        // attn[z] = P V
        gemm(scor, v, attn, 1024, HDIM, 1024, 1024, DDIM, DDIM,
             nullptr, nullptr, nullptr, 1.f, 0, 2, 64, false);

        // x = x + attn @ Wo + bo
        gemm(attn, wo, x, MROWS, DDIM, DDIM, DDIM, DDIM, DDIM,
             bo + l * DDIM, x, nullptr, 1.f, 0, 0, 1, false);

        layernorm_k<<<MROWS, 256>>>(x, h, ln2_g + l * DDIM, ln2_b + l * DDIM);

        // mlp = gelu(h @ W1 + b1)
        gemm(h, w1, mlp, MROWS, IDIM, DDIM, DDIM, IDIM, IDIM,
             b1 + l * IDIM, nullptr, nullptr, 1.f, FLAG_GELU, 0, 1, false);

        // x = x + mlp @ W2 + b2
        gemm(mlp, w2, x, MROWS, DDIM, IDIM, IDIM, DDIM, DDIM,
             b2 + l * DDIM, x, nullptr, 1.f, 0, 0, 1, false);
    }

    // 3) final layernorm -> d_out
    layernorm_k<<<MROWS, 256>>>(x, out, lnf_g, lnf_b);
}